// round 10
// baseline (speedup 1.0000x reference)
#include <cuda_runtime.h>

#define Lc   96
#define Hc   8
#define Ec   64
#define EHc  128
#define NT   256
#define NPS  3          // row-pairs per warp (6 rows); 8 warps -> 48 rows/CTA
#define GRID 128        // 128 * 48 = 6144 chains exactly
#define YP   132
#define HPP  260

constexpr int SM_W1  = 0;                     // [64][128] row-major
constexpr int SM_W2P = SM_W1 + Ec * EHc;      // [64][128] permuted
constexpr int SM_B1  = SM_W2P + Ec * EHc;
constexpr int SM_B2  = SM_B1 + EHc;
constexpr int SM_TS  = SM_B2 + Ec;
constexpr int SM_Y   = SM_TS + Lc;            // [24][132] pair-interleaved
constexpr int SM_YIN = SM_Y   + 24 * YP;
constexpr int SM_K1  = SM_YIN + 24 * YP;
constexpr int SM_K2  = SM_K1  + 24 * YP;
constexpr int SM_HP  = SM_K2  + 24 * YP;      // [24][260]
constexpr int SM_TOT = SM_HP  + 24 * HPP;
constexpr int SMEM_BYTES = SM_TOT * 4;        // ~142 KB

typedef unsigned long long ull;

__device__ __forceinline__ ull pk2(float a, float b) {
    ull r; asm("mov.b64 %0, {%1, %2};" : "=l"(r) : "f"(a), "f"(b)); return r;
}
__device__ __forceinline__ void upk2(ull v, float& a, float& b) {
    asm("mov.b64 {%0, %1}, %2;" : "=f"(a), "=f"(b) : "l"(v));
}
__device__ __forceinline__ ull f2fma(ull a, ull b, ull c) {
    ull d; asm("fma.rn.f32x2 %0, %1, %2, %3;" : "=l"(d) : "l"(a), "l"(b), "l"(c));
    return d;
}
__device__ __forceinline__ ull add2(ull a, ull b) {
    ull d; asm("add.rn.f32x2 %0, %1, %2;" : "=l"(d) : "l"(a), "l"(b)); return d;
}
__device__ __forceinline__ ull mul2(ull a, ull b) {
    ull d; asm("mul.rn.f32x2 %0, %1, %2;" : "=l"(d) : "l"(a), "l"(b)); return d;
}
__device__ __forceinline__ ull xor16(ull v) {
    return __shfl_xor_sync(0xFFFFFFFFu, v, 16);
}

// tanh(x) = (e^{2x}-1)/(e^{2x}+1), clamp |x|<=9. Abs err ~1e-7.
__device__ __forceinline__ float fast_tanh(float x) {
    float xc = fminf(fmaxf(x, -9.0f), 9.0f);
    float t;
    asm("ex2.approx.f32 %0, %1;" : "=f"(t) : "f"(xc * 2.8853900817779268f));
    float r;
    asm("rcp.approx.f32 %0, %1;" : "=f"(r) : "f"(t + 1.0f));
    return (t - 1.0f) * r;
}

// GEMM1: Hp = tanh(Yin@W1 + b1). k-split: half hb sums e in [32hb, 32hb+32).
// Lane (hb,cg2): cols 8cg2..8cg2+7, acc f32x2 over (rowA,rowB) per pair.
// After shfl-combine, duty cols c4+4hb are tanh'd and stored.
// Hidden pair for col j stored at pair-row offset 64*(j&3) + 2*(j>>2).
__device__ __forceinline__ void gemm1(float* sm, int ybase, int cg2, int hb, int pb) {
    const float* __restrict__ W1 = sm + SM_W1;
    ull acc[NPS][8];
    {
        float4 bl = *(const float4*)&sm[SM_B1 + 8 * cg2];
        float4 bh = *(const float4*)&sm[SM_B1 + 8 * cg2 + 4];
        ull b[8];
        b[0] = hb ? 0ull : pk2(bl.x, bl.x);
        b[1] = hb ? 0ull : pk2(bl.y, bl.y);
        b[2] = hb ? 0ull : pk2(bl.z, bl.z);
        b[3] = hb ? 0ull : pk2(bl.w, bl.w);
        b[4] = hb ? 0ull : pk2(bh.x, bh.x);
        b[5] = hb ? 0ull : pk2(bh.y, bh.y);
        b[6] = hb ? 0ull : pk2(bh.z, bh.z);
        b[7] = hb ? 0ull : pk2(bh.w, bh.w);
#pragma unroll
        for (int p = 0; p < NPS; ++p)
#pragma unroll
            for (int c = 0; c < 8; ++c) acc[p][c] = b[c];
    }
#pragma unroll 4
    for (int eb = 0; eb < 16; ++eb) {
        const float* wr = W1 + (2 * eb + 32 * hb) * EHc + 8 * cg2;
        float4 w0a = *(const float4*)(wr);
        float4 w0b = *(const float4*)(wr + 4);
        float4 w1a = *(const float4*)(wr + EHc);
        float4 w1b = *(const float4*)(wr + EHc + 4);
        ull w0[8], w1[8];
        w0[0] = pk2(w0a.x, w0a.x); w0[1] = pk2(w0a.y, w0a.y);
        w0[2] = pk2(w0a.z, w0a.z); w0[3] = pk2(w0a.w, w0a.w);
        w0[4] = pk2(w0b.x, w0b.x); w0[5] = pk2(w0b.y, w0b.y);
        w0[6] = pk2(w0b.z, w0b.z); w0[7] = pk2(w0b.w, w0b.w);
        w1[0] = pk2(w1a.x, w1a.x); w1[1] = pk2(w1a.y, w1a.y);
        w1[2] = pk2(w1a.z, w1a.z); w1[3] = pk2(w1a.w, w1a.w);
        w1[4] = pk2(w1b.x, w1b.x); w1[5] = pk2(w1b.y, w1b.y);
        w1[6] = pk2(w1b.z, w1b.z); w1[7] = pk2(w1b.w, w1b.w);
#pragma unroll
        for (int p = 0; p < NPS; ++p) {
            ulonglong2 yv =
                *(const ulonglong2*)&sm[ybase + (pb + p) * YP + 4 * eb + 64 * hb];
#pragma unroll
            for (int c = 0; c < 8; ++c) {
                acc[p][c] = f2fma(yv.x, w0[c], acc[p][c]);
                acc[p][c] = f2fma(yv.y, w1[c], acc[p][c]);
            }
        }
    }
    // combine halves
#pragma unroll
    for (int p = 0; p < NPS; ++p)
#pragma unroll
        for (int c = 0; c < 8; ++c) acc[p][c] = add2(acc[p][c], xor16(acc[p][c]));
    // tanh + store duty cols (c4 + 4*hb)
#pragma unroll
    for (int p = 0; p < NPS; ++p) {
        float* hr = sm + SM_HP + (pb + p) * HPP;
#pragma unroll
        for (int c4 = 0; c4 < 4; ++c4) {
            ull v = hb ? acc[p][c4 + 4] : acc[p][c4];
            float a, b;
            upk2(v, a, b);
            *(float2*)&hr[64 * c4 + 4 * cg2 + 2 * hb] =
                make_float2(fast_tanh(a), fast_tanh(b));
        }
    }
}

// GEMM2 + RK4 stage. k-split over j (half hb sums u in [32hb, 32hb+32)).
// Lane (hb,cg2): acc cols 4cg2..4cg2+3; after combine, epilogue on cols
// ec = 4cg2 + 2hb (local acc idx 2hb, 2hb+1).
template <int ST>
__device__ __forceinline__ void gemm2_epi(float* sm, int cg2, int hb, int pb,
                                          const ull dp[NPS], const float4 x0p[NPS],
                                          const int joA[NPS], const int joB[NPS],
                                          unsigned rstAm, unsigned rstBm,
                                          float* __restrict__ out) {
    const float* __restrict__ W2 = sm + SM_W2P;
    ull acc[NPS][4];
    {
        float4 bv = *(const float4*)&sm[SM_B2 + 4 * cg2];
        ull b[4];
        b[0] = hb ? 0ull : pk2(bv.x, bv.x);
        b[1] = hb ? 0ull : pk2(bv.y, bv.y);
        b[2] = hb ? 0ull : pk2(bv.z, bv.z);
        b[3] = hb ? 0ull : pk2(bv.w, bv.w);
#pragma unroll
        for (int p = 0; p < NPS; ++p)
#pragma unroll
            for (int c = 0; c < 4; ++c) acc[p][c] = b[c];
    }
#pragma unroll 4
    for (int ui = 0; ui < 32; ++ui) {
        const float* wr = W2 + (ui + 32 * hb) * EHc + 8 * cg2;
        float4 wA = *(const float4*)(wr);      // w[j0][4 cols]
        float4 wB = *(const float4*)(wr + 4);  // w[j0+4][4 cols]
        ull w0[4], w1[4];
        w0[0] = pk2(wA.x, wA.x); w0[1] = pk2(wA.y, wA.y);
        w0[2] = pk2(wA.z, wA.z); w0[3] = pk2(wA.w, wA.w);
        w1[0] = pk2(wB.x, wB.x); w1[1] = pk2(wB.y, wB.y);
        w1[2] = pk2(wB.z, wB.z); w1[3] = pk2(wB.w, wB.w);
#pragma unroll
        for (int p = 0; p < NPS; ++p) {
            ulonglong2 hv =
                *(const ulonglong2*)&sm[SM_HP + (pb + p) * HPP + 4 * ui + 128 * hb];
#pragma unroll
            for (int c = 0; c < 4; ++c) {
                acc[p][c] = f2fma(hv.x, w0[c], acc[p][c]);
                acc[p][c] = f2fma(hv.y, w1[c], acc[p][c]);
            }
        }
    }
#pragma unroll
    for (int p = 0; p < NPS; ++p)
#pragma unroll
        for (int c = 0; c < 4; ++c) acc[p][c] = add2(acc[p][c], xor16(acc[p][c]));

    const ull THIRDC  = pk2(1.0f / 3.0f, 1.0f / 3.0f);
    const ull NTHIRDC = pk2(-1.0f / 3.0f, -1.0f / 3.0f);
    const ull EIGHTHC = pk2(0.125f, 0.125f);
    const ull THREEC  = pk2(3.0f, 3.0f);
    const ull NEGONEC = pk2(-1.0f, -1.0f);

#pragma unroll
    for (int p = 0; p < NPS; ++p) {
        int off = (pb + p) * YP + 8 * cg2 + 4 * hb;
        float* yr  = sm + SM_Y   + off;
        float* yi  = sm + SM_YIN + off;
        float* k1r = sm + SM_K1  + off;
        float* k2r = sm + SM_K2  + off;
        ulonglong2 yv = *(const ulonglong2*)yr;
        ull o0 = hb ? acc[p][2] : acc[p][0];
        ull o1 = hb ? acc[p][3] : acc[p][1];
        ull d = dp[p];
        if (ST == 0) {
            *(ulonglong2*)k1r = make_ulonglong2(o0, o1);
            ull d3 = mul2(d, THIRDC);
            *(ulonglong2*)yi = make_ulonglong2(f2fma(o0, d3, yv.x),
                                               f2fma(o1, d3, yv.y));
        } else if (ST == 1) {
            ulonglong2 k1 = *(const ulonglong2*)k1r;
            *(ulonglong2*)k2r = make_ulonglong2(o0, o1);
            ull nd3 = mul2(d, NTHIRDC);
            ull t0 = f2fma(k1.x, nd3, yv.x);
            ull t1 = f2fma(k1.y, nd3, yv.y);
            *(ulonglong2*)yi = make_ulonglong2(f2fma(o0, d, t0), f2fma(o1, d, t1));
        } else if (ST == 2) {
            ulonglong2 k1 = *(const ulonglong2*)k1r;
            ulonglong2 k2 = *(const ulonglong2*)k2r;
            ull s0 = add2(k2.x, o0), s1 = add2(k2.y, o1);
            *(ulonglong2*)k1r = make_ulonglong2(f2fma(s0, THREEC, k1.x),
                                                f2fma(s1, THREEC, k1.y));
            ull a0 = add2(k1.x, o0), a1 = add2(k1.y, o1);
            ull u0 = f2fma(k2.x, NEGONEC, a0);
            ull u1 = f2fma(k2.y, NEGONEC, a1);
            *(ulonglong2*)yi = make_ulonglong2(f2fma(u0, d, yv.x),
                                               f2fma(u1, d, yv.y));
        } else {
            ulonglong2 k1 = *(const ulonglong2*)k1r;
            ull d8 = mul2(d, EIGHTHC);
            ull yn0 = f2fma(add2(k1.x, o0), d8, yv.x);
            ull yn1 = f2fma(add2(k1.y, o1), d8, yv.y);
            float yA0, yB0, yA1, yB1;
            upk2(yn0, yA0, yB0);
            upk2(yn1, yA1, yB1);
            *(float4*)&out[joA[p]] = make_float4(x0p[p].x, yA0, x0p[p].y, yA1);
            *(float4*)&out[joB[p]] = make_float4(x0p[p].z, yB0, x0p[p].w, yB1);
            bool rA = (rstAm >> p) & 1, rB = (rstBm >> p) & 1;
            *(float4*)yr = make_float4(rA ? x0p[p].x : yA0, rB ? x0p[p].z : yB0,
                                       rA ? x0p[p].y : yA1, rB ? x0p[p].w : yB1);
        }
    }
}

__global__ void __launch_bounds__(NT, 1)
ode_kernel(const float* __restrict__ x, const float* __restrict__ tsg,
           const float* __restrict__ W1g, const float* __restrict__ b1g,
           const float* __restrict__ W2g, const float* __restrict__ b2g,
           float* __restrict__ out) {
    extern __shared__ float sm[];
    const int tid = threadIdx.x;
    const int lane = tid & 31;
    const int cg2 = lane & 15;
    const int hb  = lane >> 4;
    const int wid = tid >> 5;
    const int pb  = wid * NPS;

    // W1 row-major copy
    for (int t = tid; t < Ec * EHc; t += NT) sm[SM_W1 + t] = W1g[t];
    // W2 permuted for the HP layout: W2P[u][8c+k] = W2[j0(u)+4*(k>>2)][4c+(k&3)],
    // j0(u) = 8*(u&15) + (u>>4)
    for (int t = tid; t < 64 * 128; t += NT) {
        int u = t >> 7, p = t & 127, c = p >> 3, k = p & 7;
        int j = 8 * (u & 15) + (u >> 4) + 4 * (k >> 2);
        sm[SM_W2P + t] = W2g[j * Ec + 4 * c + (k & 3)];
    }
    if (tid < EHc) sm[SM_B1 + tid] = b1g[tid];
    if (tid < Ec)  sm[SM_B2 + tid] = b2g[tid];
    if (tid < Lc)  sm[SM_TS + tid] = tsg[tid];

    // chain metadata: 48 rows/CTA exact, lane owns cols ec, ec+1
    const int qbase = blockIdx.x * 48 + wid * 6;
    const int ec = 4 * cg2 + 2 * hb;
    float4 x0p[NPS];
    int obA[NPS], obB[NPS], idxA[NPS], idxB[NPS];
#pragma unroll
    for (int p = 0; p < NPS; ++p) {
        int qA = qbase + 2 * p, qB = qbase + 2 * p + 1;
        idxA[p] = qA >> 6; idxB[p] = qB >> 6;
        int bA = (qA >> 3) & 7, hA = qA & 7;
        int bB = (qB >> 3) & 7, hB = qB & 7;
        float2 xA = *(const float2*)&x[((bA * Lc + idxA[p]) * Hc + hA) * Ec + ec];
        float2 xB = *(const float2*)&x[((bB * Lc + idxB[p]) * Hc + hB) * Ec + ec];
        x0p[p] = make_float4(xA.x, xA.y, xB.x, xB.y);
        obA[p] = bA * (Lc * Lc * Hc * Ec * 2) + idxA[p] * (Lc * Hc * Ec * 2) +
                 hA * (Ec * 2) + 2 * ec;
        obB[p] = bB * (Lc * Lc * Hc * Ec * 2) + idxB[p] * (Lc * Hc * Ec * 2) +
                 hB * (Ec * 2) + 2 * ec;
        *(float4*)&sm[SM_Y + (pb + p) * YP + 2 * ec] =
            make_float4(xA.x, xB.x, xA.y, xB.y);
        *(float4*)&out[obA[p] + idxA[p] * (Hc * Ec * 2)] =
            make_float4(xA.x, xA.x, xA.y, xA.y);
        *(float4*)&out[obB[p] + idxB[p] * (Hc * Ec * 2)] =
            make_float4(xB.x, xB.x, xB.y, xB.y);
    }
    __syncthreads();   // weights + ts visible; warps free-run

    const float* ts = sm + SM_TS;

    // 95 lockstep RK4 steps: fwd k < nf = 95-idx (emit j=s+1), reset to x0,
    // then bwd (dt<0, emit j=s-1). Rows warp-private -> __syncwarp only.
    for (int k = 0; k < Lc - 1; ++k) {
        ull dp[NPS];
        int joA[NPS], joB[NPS];
        unsigned rstAm = 0, rstBm = 0;
#pragma unroll
        for (int p = 0; p < NPS; ++p) {
            float dA, dB; int jA, jB;
            {
                int idx = idxA[p], nf = (Lc - 1) - idx;
                if (k < nf) {
                    int s = idx + k;
                    dA = ts[s + 1] - ts[s]; jA = s + 1;
                    if (k + 1 == nf) rstAm |= 1u << p;
                } else {
                    int s = idx - (k - nf);
                    dA = ts[s - 1] - ts[s]; jA = s - 1;
                }
            }
            {
                int idx = idxB[p], nf = (Lc - 1) - idx;
                if (k < nf) {
                    int s = idx + k;
                    dB = ts[s + 1] - ts[s]; jB = s + 1;
                    if (k + 1 == nf) rstBm |= 1u << p;
                } else {
                    int s = idx - (k - nf);
                    dB = ts[s - 1] - ts[s]; jB = s - 1;
                }
            }
            dp[p] = pk2(dA, dB);
            joA[p] = obA[p] + jA * (Hc * Ec * 2);
            joB[p] = obB[p] + jB * (Hc * Ec * 2);
        }

        gemm1(sm, SM_Y, cg2, hb, pb);
        __syncwarp();
        gemm2_epi<0>(sm, cg2, hb, pb, dp, x0p, joA, joB, rstAm, rstBm, out);
        __syncwarp();
        gemm1(sm, SM_YIN, cg2, hb, pb);
        __syncwarp();
        gemm2_epi<1>(sm, cg2, hb, pb, dp, x0p, joA, joB, rstAm, rstBm, out);
        __syncwarp();
        gemm1(sm, SM_YIN, cg2, hb, pb);
        __syncwarp();
        gemm2_epi<2>(sm, cg2, hb, pb, dp, x0p, joA, joB, rstAm, rstBm, out);
        __syncwarp();
        gemm1(sm, SM_YIN, cg2, hb, pb);
        __syncwarp();
        gemm2_epi<3>(sm, cg2, hb, pb, dp, x0p, joA, joB, rstAm, rstBm, out);
        __syncwarp();
    }
}

extern "C" void kernel_launch(void* const* d_in, const int* in_sizes, int n_in,
                              void* d_out, int out_size) {
    const float* x   = (const float*)d_in[0];
    const float* ts  = (const float*)d_in[1];
    const float* W1  = (const float*)d_in[2];
    const float* b1  = (const float*)d_in[3];
    const float* W2  = (const float*)d_in[4];
    const float* b2  = (const float*)d_in[5];
    float* out = (float*)d_out;

    cudaFuncSetAttribute(ode_kernel, cudaFuncAttributeMaxDynamicSharedMemorySize,
                         SMEM_BYTES);
    ode_kernel<<<GRID, NT, SMEM_BYTES>>>(x, ts, W1, b1, W2, b2, out);
}

// round 11
// speedup vs baseline: 1.0008x; 1.0008x over previous
#include <cuda_runtime.h>

#define Lc   96
#define Hc   8
#define Ec   64
#define EHc  128
#define NT   256
#define NPS  3          // row-pairs per warp (6 rows); 8 warps -> 48 rows/CTA
#define GRID 128        // 128 * 48 = 6144 chains exactly
#define YP   132
#define HPP  260

constexpr int SM_W1  = 0;                     // [64][128] row-major
constexpr int SM_W2P = SM_W1 + Ec * EHc;      // [64][128] permuted
constexpr int SM_B1  = SM_W2P + Ec * EHc;
constexpr int SM_B2  = SM_B1 + EHc;
constexpr int SM_TS  = SM_B2 + Ec;
constexpr int SM_Y   = SM_TS + Lc;            // [24][132] pair-interleaved
constexpr int SM_YIN = SM_Y   + 24 * YP;
constexpr int SM_K1  = SM_YIN + 24 * YP;
constexpr int SM_K2  = SM_K1  + 24 * YP;
constexpr int SM_HP  = SM_K2  + 24 * YP;      // [24][260]
constexpr int SM_TOT = SM_HP  + 24 * HPP;
constexpr int SMEM_BYTES = SM_TOT * 4;        // ~142 KB

typedef unsigned long long ull;

__device__ __forceinline__ ull pk2(float a, float b) {
    ull r; asm("mov.b64 %0, {%1, %2};" : "=l"(r) : "f"(a), "f"(b)); return r;
}
__device__ __forceinline__ void upk2(ull v, float& a, float& b) {
    asm("mov.b64 {%0, %1}, %2;" : "=f"(a), "=f"(b) : "l"(v));
}
__device__ __forceinline__ ull f2fma(ull a, ull b, ull c) {
    ull d; asm("fma.rn.f32x2 %0, %1, %2, %3;" : "=l"(d) : "l"(a), "l"(b), "l"(c));
    return d;
}
__device__ __forceinline__ ull add2(ull a, ull b) {
    ull d; asm("add.rn.f32x2 %0, %1, %2;" : "=l"(d) : "l"(a), "l"(b)); return d;
}
__device__ __forceinline__ ull mul2(ull a, ull b) {
    ull d; asm("mul.rn.f32x2 %0, %1, %2;" : "=l"(d) : "l"(a), "l"(b)); return d;
}
__device__ __forceinline__ ull xor16(ull v) {
    return __shfl_xor_sync(0xFFFFFFFFu, v, 16);
}

// tanh(x) = (e^{2x}-1)/(e^{2x}+1), clamp |x|<=9. Abs err ~1e-7.
__device__ __forceinline__ float fast_tanh(float x) {
    float xc = fminf(fmaxf(x, -9.0f), 9.0f);
    float t;
    asm("ex2.approx.f32 %0, %1;" : "=f"(t) : "f"(xc * 2.8853900817779268f));
    float r;
    asm("rcp.approx.f32 %0, %1;" : "=f"(r) : "f"(t + 1.0f));
    return (t - 1.0f) * r;
}

// GEMM1: Hp = tanh(Yin@W1 + b1). k-split: half hb sums e in [32hb, 32hb+32).
// Lane (hb,cg2): cols 8cg2..8cg2+7, acc f32x2 over (rowA,rowB) per pair.
// After shfl-combine, duty cols c4+4hb are tanh'd and stored.
// Hidden pair for col j stored at pair-row offset 64*(j&3) + 2*(j>>2).
__device__ __forceinline__ void gemm1(float* sm, int ybase, int cg2, int hb, int pb) {
    const float* __restrict__ W1 = sm + SM_W1;
    ull acc[NPS][8];
    {
        float4 bl = *(const float4*)&sm[SM_B1 + 8 * cg2];
        float4 bh = *(const float4*)&sm[SM_B1 + 8 * cg2 + 4];
        ull b[8];
        b[0] = hb ? 0ull : pk2(bl.x, bl.x);
        b[1] = hb ? 0ull : pk2(bl.y, bl.y);
        b[2] = hb ? 0ull : pk2(bl.z, bl.z);
        b[3] = hb ? 0ull : pk2(bl.w, bl.w);
        b[4] = hb ? 0ull : pk2(bh.x, bh.x);
        b[5] = hb ? 0ull : pk2(bh.y, bh.y);
        b[6] = hb ? 0ull : pk2(bh.z, bh.z);
        b[7] = hb ? 0ull : pk2(bh.w, bh.w);
#pragma unroll
        for (int p = 0; p < NPS; ++p)
#pragma unroll
            for (int c = 0; c < 8; ++c) acc[p][c] = b[c];
    }
#pragma unroll 4
    for (int eb = 0; eb < 16; ++eb) {
        const float* wr = W1 + (2 * eb + 32 * hb) * EHc + 8 * cg2;
        float4 w0a = *(const float4*)(wr);
        float4 w0b = *(const float4*)(wr + 4);
        float4 w1a = *(const float4*)(wr + EHc);
        float4 w1b = *(const float4*)(wr + EHc + 4);
        ull w0[8], w1[8];
        w0[0] = pk2(w0a.x, w0a.x); w0[1] = pk2(w0a.y, w0a.y);
        w0[2] = pk2(w0a.z, w0a.z); w0[3] = pk2(w0a.w, w0a.w);
        w0[4] = pk2(w0b.x, w0b.x); w0[5] = pk2(w0b.y, w0b.y);
        w0[6] = pk2(w0b.z, w0b.z); w0[7] = pk2(w0b.w, w0b.w);
        w1[0] = pk2(w1a.x, w1a.x); w1[1] = pk2(w1a.y, w1a.y);
        w1[2] = pk2(w1a.z, w1a.z); w1[3] = pk2(w1a.w, w1a.w);
        w1[4] = pk2(w1b.x, w1b.x); w1[5] = pk2(w1b.y, w1b.y);
        w1[6] = pk2(w1b.z, w1b.z); w1[7] = pk2(w1b.w, w1b.w);
#pragma unroll
        for (int p = 0; p < NPS; ++p) {
            ulonglong2 yv =
                *(const ulonglong2*)&sm[ybase + (pb + p) * YP + 4 * eb + 64 * hb];
#pragma unroll
            for (int c = 0; c < 8; ++c) {
                acc[p][c] = f2fma(yv.x, w0[c], acc[p][c]);
                acc[p][c] = f2fma(yv.y, w1[c], acc[p][c]);
            }
        }
    }
    // combine halves
#pragma unroll
    for (int p = 0; p < NPS; ++p)
#pragma unroll
        for (int c = 0; c < 8; ++c) acc[p][c] = add2(acc[p][c], xor16(acc[p][c]));
    // tanh + store duty cols (c4 + 4*hb)
#pragma unroll
    for (int p = 0; p < NPS; ++p) {
        float* hr = sm + SM_HP + (pb + p) * HPP;
#pragma unroll
        for (int c4 = 0; c4 < 4; ++c4) {
            ull v = hb ? acc[p][c4 + 4] : acc[p][c4];
            float a, b;
            upk2(v, a, b);
            *(float2*)&hr[64 * c4 + 4 * cg2 + 2 * hb] =
                make_float2(fast_tanh(a), fast_tanh(b));
        }
    }
}

// GEMM2 + RK4 stage. k-split over j (half hb sums u in [32hb, 32hb+32)).
// Lane (hb,cg2): acc cols 4cg2..4cg2+3; after combine, epilogue on cols
// ec = 4cg2 + 2hb (local acc idx 2hb, 2hb+1).
template <int ST>
__device__ __forceinline__ void gemm2_epi(float* sm, int cg2, int hb, int pb,
                                          const ull dp[NPS], const float4 x0p[NPS],
                                          const int joA[NPS], const int joB[NPS],
                                          unsigned rstAm, unsigned rstBm,
                                          float* __restrict__ out) {
    const float* __restrict__ W2 = sm + SM_W2P;
    ull acc[NPS][4];
    {
        float4 bv = *(const float4*)&sm[SM_B2 + 4 * cg2];
        ull b[4];
        b[0] = hb ? 0ull : pk2(bv.x, bv.x);
        b[1] = hb ? 0ull : pk2(bv.y, bv.y);
        b[2] = hb ? 0ull : pk2(bv.z, bv.z);
        b[3] = hb ? 0ull : pk2(bv.w, bv.w);
#pragma unroll
        for (int p = 0; p < NPS; ++p)
#pragma unroll
            for (int c = 0; c < 4; ++c) acc[p][c] = b[c];
    }
#pragma unroll 4
    for (int ui = 0; ui < 32; ++ui) {
        const float* wr = W2 + (ui + 32 * hb) * EHc + 8 * cg2;
        float4 wA = *(const float4*)(wr);      // w[j0][4 cols]
        float4 wB = *(const float4*)(wr + 4);  // w[j0+4][4 cols]
        ull w0[4], w1[4];
        w0[0] = pk2(wA.x, wA.x); w0[1] = pk2(wA.y, wA.y);
        w0[2] = pk2(wA.z, wA.z); w0[3] = pk2(wA.w, wA.w);
        w1[0] = pk2(wB.x, wB.x); w1[1] = pk2(wB.y, wB.y);
        w1[2] = pk2(wB.z, wB.z); w1[3] = pk2(wB.w, wB.w);
#pragma unroll
        for (int p = 0; p < NPS; ++p) {
            ulonglong2 hv =
                *(const ulonglong2*)&sm[SM_HP + (pb + p) * HPP + 4 * ui + 128 * hb];
#pragma unroll
            for (int c = 0; c < 4; ++c) {
                acc[p][c] = f2fma(hv.x, w0[c], acc[p][c]);
                acc[p][c] = f2fma(hv.y, w1[c], acc[p][c]);
            }
        }
    }
#pragma unroll
    for (int p = 0; p < NPS; ++p)
#pragma unroll
        for (int c = 0; c < 4; ++c) acc[p][c] = add2(acc[p][c], xor16(acc[p][c]));

    const ull THIRDC  = pk2(1.0f / 3.0f, 1.0f / 3.0f);
    const ull NTHIRDC = pk2(-1.0f / 3.0f, -1.0f / 3.0f);
    const ull EIGHTHC = pk2(0.125f, 0.125f);
    const ull THREEC  = pk2(3.0f, 3.0f);
    const ull NEGONEC = pk2(-1.0f, -1.0f);

#pragma unroll
    for (int p = 0; p < NPS; ++p) {
        int off = (pb + p) * YP + 8 * cg2 + 4 * hb;
        float* yr  = sm + SM_Y   + off;
        float* yi  = sm + SM_YIN + off;
        float* k1r = sm + SM_K1  + off;
        float* k2r = sm + SM_K2  + off;
        ulonglong2 yv = *(const ulonglong2*)yr;
        ull o0 = hb ? acc[p][2] : acc[p][0];
        ull o1 = hb ? acc[p][3] : acc[p][1];
        ull d = dp[p];
        if (ST == 0) {
            *(ulonglong2*)k1r = make_ulonglong2(o0, o1);
            ull d3 = mul2(d, THIRDC);
            *(ulonglong2*)yi = make_ulonglong2(f2fma(o0, d3, yv.x),
                                               f2fma(o1, d3, yv.y));
        } else if (ST == 1) {
            ulonglong2 k1 = *(const ulonglong2*)k1r;
            *(ulonglong2*)k2r = make_ulonglong2(o0, o1);
            ull nd3 = mul2(d, NTHIRDC);
            ull t0 = f2fma(k1.x, nd3, yv.x);
            ull t1 = f2fma(k1.y, nd3, yv.y);
            *(ulonglong2*)yi = make_ulonglong2(f2fma(o0, d, t0), f2fma(o1, d, t1));
        } else if (ST == 2) {
            ulonglong2 k1 = *(const ulonglong2*)k1r;
            ulonglong2 k2 = *(const ulonglong2*)k2r;
            ull s0 = add2(k2.x, o0), s1 = add2(k2.y, o1);
            *(ulonglong2*)k1r = make_ulonglong2(f2fma(s0, THREEC, k1.x),
                                                f2fma(s1, THREEC, k1.y));
            ull a0 = add2(k1.x, o0), a1 = add2(k1.y, o1);
            ull u0 = f2fma(k2.x, NEGONEC, a0);
            ull u1 = f2fma(k2.y, NEGONEC, a1);
            *(ulonglong2*)yi = make_ulonglong2(f2fma(u0, d, yv.x),
                                               f2fma(u1, d, yv.y));
        } else {
            ulonglong2 k1 = *(const ulonglong2*)k1r;
            ull d8 = mul2(d, EIGHTHC);
            ull yn0 = f2fma(add2(k1.x, o0), d8, yv.x);
            ull yn1 = f2fma(add2(k1.y, o1), d8, yv.y);
            float yA0, yB0, yA1, yB1;
            upk2(yn0, yA0, yB0);
            upk2(yn1, yA1, yB1);
            *(float4*)&out[joA[p]] = make_float4(x0p[p].x, yA0, x0p[p].y, yA1);
            *(float4*)&out[joB[p]] = make_float4(x0p[p].z, yB0, x0p[p].w, yB1);
            bool rA = (rstAm >> p) & 1, rB = (rstBm >> p) & 1;
            *(float4*)yr = make_float4(rA ? x0p[p].x : yA0, rB ? x0p[p].z : yB0,
                                       rA ? x0p[p].y : yA1, rB ? x0p[p].w : yB1);
        }
    }
}

__global__ void __launch_bounds__(NT, 1)
ode_kernel(const float* __restrict__ x, const float* __restrict__ tsg,
           const float* __restrict__ W1g, const float* __restrict__ b1g,
           const float* __restrict__ W2g, const float* __restrict__ b2g,
           float* __restrict__ out) {
    extern __shared__ float sm[];
    const int tid = threadIdx.x;
    const int lane = tid & 31;
    const int cg2 = lane & 15;
    const int hb  = lane >> 4;
    const int wid = tid >> 5;
    const int pb  = wid * NPS;

    // W1 row-major copy
    for (int t = tid; t < Ec * EHc; t += NT) sm[SM_W1 + t] = W1g[t];
    // W2 permuted for the HP layout: W2P[u][8c+k] = W2[j0(u)+4*(k>>2)][4c+(k&3)],
    // j0(u) = 8*(u&15) + (u>>4)
    for (int t = tid; t < 64 * 128; t += NT) {
        int u = t >> 7, p = t & 127, c = p >> 3, k = p & 7;
        int j = 8 * (u & 15) + (u >> 4) + 4 * (k >> 2);
        sm[SM_W2P + t] = W2g[j * Ec + 4 * c + (k & 3)];
    }
    if (tid < EHc) sm[SM_B1 + tid] = b1g[tid];
    if (tid < Ec)  sm[SM_B2 + tid] = b2g[tid];
    if (tid < Lc)  sm[SM_TS + tid] = tsg[tid];

    // chain metadata: 48 rows/CTA exact, lane owns cols ec, ec+1
    const int qbase = blockIdx.x * 48 + wid * 6;
    const int ec = 4 * cg2 + 2 * hb;
    float4 x0p[NPS];
    int obA[NPS], obB[NPS], idxA[NPS], idxB[NPS];
#pragma unroll
    for (int p = 0; p < NPS; ++p) {
        int qA = qbase + 2 * p, qB = qbase + 2 * p + 1;
        idxA[p] = qA >> 6; idxB[p] = qB >> 6;
        int bA = (qA >> 3) & 7, hA = qA & 7;
        int bB = (qB >> 3) & 7, hB = qB & 7;
        float2 xA = *(const float2*)&x[((bA * Lc + idxA[p]) * Hc + hA) * Ec + ec];
        float2 xB = *(const float2*)&x[((bB * Lc + idxB[p]) * Hc + hB) * Ec + ec];
        x0p[p] = make_float4(xA.x, xA.y, xB.x, xB.y);
        obA[p] = bA * (Lc * Lc * Hc * Ec * 2) + idxA[p] * (Lc * Hc * Ec * 2) +
                 hA * (Ec * 2) + 2 * ec;
        obB[p] = bB * (Lc * Lc * Hc * Ec * 2) + idxB[p] * (Lc * Hc * Ec * 2) +
                 hB * (Ec * 2) + 2 * ec;
        *(float4*)&sm[SM_Y + (pb + p) * YP + 2 * ec] =
            make_float4(xA.x, xB.x, xA.y, xB.y);
        *(float4*)&out[obA[p] + idxA[p] * (Hc * Ec * 2)] =
            make_float4(xA.x, xA.x, xA.y, xA.y);
        *(float4*)&out[obB[p] + idxB[p] * (Hc * Ec * 2)] =
            make_float4(xB.x, xB.x, xB.y, xB.y);
    }
    __syncthreads();   // weights + ts visible; warps free-run

    const float* ts = sm + SM_TS;

    // 95 lockstep RK4 steps: fwd k < nf = 95-idx (emit j=s+1), reset to x0,
    // then bwd (dt<0, emit j=s-1). Rows warp-private -> __syncwarp only.
    for (int k = 0; k < Lc - 1; ++k) {
        ull dp[NPS];
        int joA[NPS], joB[NPS];
        unsigned rstAm = 0, rstBm = 0;
#pragma unroll
        for (int p = 0; p < NPS; ++p) {
            float dA, dB; int jA, jB;
            {
                int idx = idxA[p], nf = (Lc - 1) - idx;
                if (k < nf) {
                    int s = idx + k;
                    dA = ts[s + 1] - ts[s]; jA = s + 1;
                    if (k + 1 == nf) rstAm |= 1u << p;
                } else {
                    int s = idx - (k - nf);
                    dA = ts[s - 1] - ts[s]; jA = s - 1;
                }
            }
            {
                int idx = idxB[p], nf = (Lc - 1) - idx;
                if (k < nf) {
                    int s = idx + k;
                    dB = ts[s + 1] - ts[s]; jB = s + 1;
                    if (k + 1 == nf) rstBm |= 1u << p;
                } else {
                    int s = idx - (k - nf);
                    dB = ts[s - 1] - ts[s]; jB = s - 1;
                }
            }
            dp[p] = pk2(dA, dB);
            joA[p] = obA[p] + jA * (Hc * Ec * 2);
            joB[p] = obB[p] + jB * (Hc * Ec * 2);
        }

        gemm1(sm, SM_Y, cg2, hb, pb);
        __syncwarp();
        gemm2_epi<0>(sm, cg2, hb, pb, dp, x0p, joA, joB, rstAm, rstBm, out);
        __syncwarp();
        gemm1(sm, SM_YIN, cg2, hb, pb);
        __syncwarp();
        gemm2_epi<1>(sm, cg2, hb, pb, dp, x0p, joA, joB, rstAm, rstBm, out);
        __syncwarp();
        gemm1(sm, SM_YIN, cg2, hb, pb);
        __syncwarp();
        gemm2_epi<2>(sm, cg2, hb, pb, dp, x0p, joA, joB, rstAm, rstBm, out);
        __syncwarp();
        gemm1(sm, SM_YIN, cg2, hb, pb);
        __syncwarp();
        gemm2_epi<3>(sm, cg2, hb, pb, dp, x0p, joA, joB, rstAm, rstBm, out);
        __syncwarp();
    }
}

extern "C" void kernel_launch(void* const* d_in, const int* in_sizes, int n_in,
                              void* d_out, int out_size) {
    const float* x   = (const float*)d_in[0];
    const float* ts  = (const float*)d_in[1];
    const float* W1  = (const float*)d_in[2];
    const float* b1  = (const float*)d_in[3];
    const float* W2  = (const float*)d_in[4];
    const float* b2  = (const float*)d_in[5];
    float* out = (float*)d_out;

    cudaFuncSetAttribute(ode_kernel, cudaFuncAttributeMaxDynamicSharedMemorySize,
                         SMEM_BYTES);
    ode_kernel<<<GRID, NT, SMEM_BYTES>>>(x, ts, W1, b1, W2, b2, out);
}

// round 12
// speedup vs baseline: 1.1577x; 1.1568x over previous
#include <cuda_runtime.h>

#define Lc   96
#define Hc   8
#define Ec   64
#define EHc  128
#define NT   256
#define NPS  3          // row-pairs per warp; 8 warps * 6 rows = 48 rows/CTA
#define GRID 128        // 128 * 48 = 6144 chains exactly
#define YP   132
#define HPP  260

constexpr int SM_W1  = 0;                     // [64][128] row-major
constexpr int SM_W2P = SM_W1 + Ec * EHc;      // [64][128] permuted
constexpr int SM_B1  = SM_W2P + Ec * EHc;
constexpr int SM_B2  = SM_B1 + EHc;
constexpr int SM_TS  = SM_B2 + Ec;
constexpr int SM_Y   = SM_TS + Lc;            // [24][132] pair-interleaved
constexpr int SM_YIN = SM_Y   + 24 * YP;
constexpr int SM_K1  = SM_YIN + 24 * YP;
constexpr int SM_K2  = SM_K1  + 24 * YP;
constexpr int SM_HP  = SM_K2  + 24 * YP;      // [24][260]
constexpr int SM_TOT = SM_HP  + 24 * HPP;
constexpr int SMEM_BYTES = SM_TOT * 4;        // ~142 KB

typedef unsigned long long ull;

__device__ __forceinline__ ull pk2(float a, float b) {
    ull r; asm("mov.b64 %0, {%1, %2};" : "=l"(r) : "f"(a), "f"(b)); return r;
}
__device__ __forceinline__ void upk2(ull v, float& a, float& b) {
    asm("mov.b64 {%0, %1}, %2;" : "=f"(a), "=f"(b) : "l"(v));
}
__device__ __forceinline__ ull f2fma(ull a, ull b, ull c) {
    ull d; asm("fma.rn.f32x2 %0, %1, %2, %3;" : "=l"(d) : "l"(a), "l"(b), "l"(c));
    return d;
}
__device__ __forceinline__ ull add2(ull a, ull b) {
    ull d; asm("add.rn.f32x2 %0, %1, %2;" : "=l"(d) : "l"(a), "l"(b)); return d;
}
__device__ __forceinline__ ull mul2(ull a, ull b) {
    ull d; asm("mul.rn.f32x2 %0, %1, %2;" : "=l"(d) : "l"(a), "l"(b)); return d;
}

// tanh(x) = (e^{2x}-1)/(e^{2x}+1), clamp |x|<=9. Abs err ~1e-7.
__device__ __forceinline__ float fast_tanh(float x) {
    float xc = fminf(fmaxf(x, -9.0f), 9.0f);
    float t;
    asm("ex2.approx.f32 %0, %1;" : "=f"(t) : "f"(xc * 2.8853900817779268f));
    float r;
    asm("rcp.approx.f32 %0, %1;" : "=f"(r) : "f"(t + 1.0f));
    return (t - 1.0f) * r;
}

// GEMM1: Hp = tanh(Yin@W1 + b1), pair-packed rows. Lane cg: cols 4cg..4cg+3.
// Hidden pair for col j stored at pair-row offset 64*(j&3) + 2*(j>>2).
__device__ __forceinline__ void gemm1(float* sm, int ybase, int cg, int pb) {
    const float* __restrict__ W1 = sm + SM_W1;
    float4 bv = *(const float4*)&sm[SM_B1 + 4 * cg];
    ull acc[NPS][4];
    {
        ull b0 = pk2(bv.x, bv.x), b1 = pk2(bv.y, bv.y);
        ull b2 = pk2(bv.z, bv.z), b3 = pk2(bv.w, bv.w);
#pragma unroll
        for (int p = 0; p < NPS; ++p) {
            acc[p][0] = b0; acc[p][1] = b1; acc[p][2] = b2; acc[p][3] = b3;
        }
    }
#pragma unroll 4
    for (int ep = 0; ep < 32; ++ep) {
        float4 wa = *(const float4*)&W1[(2 * ep) * EHc + 4 * cg];
        float4 wb = *(const float4*)&W1[(2 * ep + 1) * EHc + 4 * cg];
        ull wa0 = pk2(wa.x, wa.x), wa1 = pk2(wa.y, wa.y);
        ull wa2 = pk2(wa.z, wa.z), wa3 = pk2(wa.w, wa.w);
        ull wb0 = pk2(wb.x, wb.x), wb1 = pk2(wb.y, wb.y);
        ull wb2 = pk2(wb.z, wb.z), wb3 = pk2(wb.w, wb.w);
#pragma unroll
        for (int p = 0; p < NPS; ++p) {
            ulonglong2 yv = *(const ulonglong2*)&sm[ybase + (pb + p) * YP + 4 * ep];
            acc[p][0] = f2fma(yv.x, wa0, acc[p][0]);
            acc[p][1] = f2fma(yv.x, wa1, acc[p][1]);
            acc[p][2] = f2fma(yv.x, wa2, acc[p][2]);
            acc[p][3] = f2fma(yv.x, wa3, acc[p][3]);
            acc[p][0] = f2fma(yv.y, wb0, acc[p][0]);
            acc[p][1] = f2fma(yv.y, wb1, acc[p][1]);
            acc[p][2] = f2fma(yv.y, wb2, acc[p][2]);
            acc[p][3] = f2fma(yv.y, wb3, acc[p][3]);
        }
    }
#pragma unroll
    for (int p = 0; p < NPS; ++p) {
        float* hr = sm + SM_HP + (pb + p) * HPP;
#pragma unroll
        for (int c = 0; c < 4; ++c) {
            float a, b;
            upk2(acc[p][c], a, b);
            *(float2*)&hr[64 * c + 2 * cg] = make_float2(fast_tanh(a), fast_tanh(b));
        }
    }
}

// GEMM2 + RK4 stage. Lane cg: out cols e = 2cg, 2cg+1 (pair-packed rows).
// ST=0: K1=o;  Yin = Y + dt/3*o
// ST=1: K2=o;  Yin = Y + dt*o - dt/3*K1
// ST=2: K1 <- K1 + 3*(K2+o); Yin = Y + dt*(K1 - K2 + o)
// ST=3: yn = Y + dt/8*(K1+o); emit {x0,yn}; Y = rst ? x0 : yn
template <int ST>
__device__ __forceinline__ void gemm2_epi(float* sm, int cg, int pb,
                                          const ull dp[NPS], const float4 x0p[NPS],
                                          const int joA[NPS], const int joB[NPS],
                                          unsigned rstAm, unsigned rstBm,
                                          float* __restrict__ out) {
    const float* __restrict__ W2 = sm + SM_W2P;
    float2 b2v = *(const float2*)&sm[SM_B2 + 2 * cg];
    ull acc[NPS][2];
    {
        ull c0 = pk2(b2v.x, b2v.x), c1 = pk2(b2v.y, b2v.y);
#pragma unroll
        for (int p = 0; p < NPS; ++p) { acc[p][0] = c0; acc[p][1] = c1; }
    }
#pragma unroll 4
    for (int u = 0; u < 64; ++u) {
        float4 w = *(const float4*)&W2[u * EHc + 4 * cg];
        ull w00 = pk2(w.x, w.x), w01 = pk2(w.y, w.y);
        ull w10 = pk2(w.z, w.z), w11 = pk2(w.w, w.w);
#pragma unroll
        for (int p = 0; p < NPS; ++p) {
            ulonglong2 hv = *(const ulonglong2*)&sm[SM_HP + (pb + p) * HPP + 4 * u];
            acc[p][0] = f2fma(hv.x, w00, acc[p][0]);
            acc[p][1] = f2fma(hv.x, w01, acc[p][1]);
            acc[p][0] = f2fma(hv.y, w10, acc[p][0]);
            acc[p][1] = f2fma(hv.y, w11, acc[p][1]);
        }
    }

    const ull THIRDC  = pk2(1.0f / 3.0f, 1.0f / 3.0f);
    const ull NTHIRDC = pk2(-1.0f / 3.0f, -1.0f / 3.0f);
    const ull EIGHTHC = pk2(0.125f, 0.125f);
    const ull THREEC  = pk2(3.0f, 3.0f);
    const ull NEGONEC = pk2(-1.0f, -1.0f);

#pragma unroll
    for (int p = 0; p < NPS; ++p) {
        float* yr  = sm + SM_Y   + (pb + p) * YP + 4 * cg;
        float* yi  = sm + SM_YIN + (pb + p) * YP + 4 * cg;
        float* k1r = sm + SM_K1  + (pb + p) * YP + 4 * cg;
        float* k2r = sm + SM_K2  + (pb + p) * YP + 4 * cg;
        ulonglong2 yv = *(const ulonglong2*)yr;
        ull o0 = acc[p][0], o1 = acc[p][1];
        ull d = dp[p];
        if (ST == 0) {
            *(ulonglong2*)k1r = make_ulonglong2(o0, o1);
            ull d3 = mul2(d, THIRDC);
            *(ulonglong2*)yi = make_ulonglong2(f2fma(o0, d3, yv.x),
                                               f2fma(o1, d3, yv.y));
        } else if (ST == 1) {
            ulonglong2 k1 = *(const ulonglong2*)k1r;
            *(ulonglong2*)k2r = make_ulonglong2(o0, o1);
            ull nd3 = mul2(d, NTHIRDC);
            ull t0 = f2fma(k1.x, nd3, yv.x);
            ull t1 = f2fma(k1.y, nd3, yv.y);
            *(ulonglong2*)yi = make_ulonglong2(f2fma(o0, d, t0), f2fma(o1, d, t1));
        } else if (ST == 2) {
            ulonglong2 k1 = *(const ulonglong2*)k1r;
            ulonglong2 k2 = *(const ulonglong2*)k2r;
            ull s0 = add2(k2.x, o0), s1 = add2(k2.y, o1);
            *(ulonglong2*)k1r = make_ulonglong2(f2fma(s0, THREEC, k1.x),
                                                f2fma(s1, THREEC, k1.y));
            ull a0 = add2(k1.x, o0), a1 = add2(k1.y, o1);
            ull u0 = f2fma(k2.x, NEGONEC, a0);
            ull u1 = f2fma(k2.y, NEGONEC, a1);
            *(ulonglong2*)yi = make_ulonglong2(f2fma(u0, d, yv.x),
                                               f2fma(u1, d, yv.y));
        } else {
            ulonglong2 k1 = *(const ulonglong2*)k1r;
            ull d8 = mul2(d, EIGHTHC);
            ull yn0 = f2fma(add2(k1.x, o0), d8, yv.x);
            ull yn1 = f2fma(add2(k1.y, o1), d8, yv.y);
            float yA0, yB0, yA1, yB1;
            upk2(yn0, yA0, yB0);
            upk2(yn1, yA1, yB1);
            *(float4*)&out[joA[p]] = make_float4(x0p[p].x, yA0, x0p[p].y, yA1);
            *(float4*)&out[joB[p]] = make_float4(x0p[p].z, yB0, x0p[p].w, yB1);
            bool rA = (rstAm >> p) & 1, rB = (rstBm >> p) & 1;
            *(float4*)yr = make_float4(rA ? x0p[p].x : yA0, rB ? x0p[p].z : yB0,
                                       rA ? x0p[p].y : yA1, rB ? x0p[p].w : yB1);
        }
    }
}

__global__ void __launch_bounds__(NT, 1)
ode_kernel(const float* __restrict__ x, const float* __restrict__ tsg,
           const float* __restrict__ W1g, const float* __restrict__ b1g,
           const float* __restrict__ W2g, const float* __restrict__ b2g,
           float* __restrict__ out) {
    extern __shared__ float sm[];
    const int tid = threadIdx.x;
    const int cg  = tid & 31;
    const int wid = tid >> 5;
    const int pb  = wid * NPS;

    // W1 row-major copy
    for (int t = tid; t < Ec * EHc; t += NT) sm[SM_W1 + t] = W1g[t];
    // W2 permuted for the HP layout: W2P[u][4c+k] = W2[j0(u)+4*(k>>1)][2c+(k&1)],
    // j0(u) = 4*(((4u)&63)>>1) + ((4u)>>6)
    for (int t = tid; t < 64 * 128; t += NT) {
        int u = t >> 7, p = t & 127, c = p >> 2, k = p & 3;
        int j0 = 4 * (((4 * u) & 63) >> 1) + ((4 * u) >> 6);
        int j = j0 + 4 * (k >> 1);
        sm[SM_W2P + t] = W2g[j * Ec + 2 * c + (k & 1)];
    }
    if (tid < EHc) sm[SM_B1 + tid] = b1g[tid];
    if (tid < Ec)  sm[SM_B2 + tid] = b2g[tid];
    if (tid < Lc)  sm[SM_TS + tid] = tsg[tid];

    // chain metadata: 48 rows/CTA, exact fit (no inactive slots).
    // q = idx*64 + b*8 + h; lane cg owns cols 2cg, 2cg+1.
    const int qbase = blockIdx.x * 48 + wid * (2 * NPS);
    float4 x0p[NPS];
    int obA[NPS], obB[NPS], idxA[NPS], idxB[NPS];
#pragma unroll
    for (int p = 0; p < NPS; ++p) {
        int qA = qbase + 2 * p, qB = qbase + 2 * p + 1;
        idxA[p] = qA >> 6; idxB[p] = qB >> 6;
        int bA = (qA >> 3) & 7, hA = qA & 7;
        int bB = (qB >> 3) & 7, hB = qB & 7;
        float2 xA = *(const float2*)&x[((bA * Lc + idxA[p]) * Hc + hA) * Ec + 2 * cg];
        float2 xB = *(const float2*)&x[((bB * Lc + idxB[p]) * Hc + hB) * Ec + 2 * cg];
        x0p[p] = make_float4(xA.x, xA.y, xB.x, xB.y);
        obA[p] = bA * (Lc * Lc * Hc * Ec * 2) + idxA[p] * (Lc * Hc * Ec * 2) +
                 hA * (Ec * 2) + 4 * cg;
        obB[p] = bB * (Lc * Lc * Hc * Ec * 2) + idxB[p] * (Lc * Hc * Ec * 2) +
                 hB * (Ec * 2) + 4 * cg;
        *(float4*)&sm[SM_Y + (pb + p) * YP + 4 * cg] =
            make_float4(xA.x, xB.x, xA.y, xB.y);
        *(float4*)&out[obA[p] + idxA[p] * (Hc * Ec * 2)] =
            make_float4(xA.x, xA.x, xA.y, xA.y);
        *(float4*)&out[obB[p] + idxB[p] * (Hc * Ec * 2)] =
            make_float4(xB.x, xB.x, xB.y, xB.y);
    }
    __syncthreads();   // weights + ts visible; warps free-run

    const float* ts = sm + SM_TS;

    // 95 lockstep RK4 steps: fwd k < nf = 95-idx (emit j=s+1), reset to x0,
    // then bwd (dt<0, emit j=s-1). Rows warp-private -> __syncwarp only.
    for (int k = 0; k < Lc - 1; ++k) {
        ull dp[NPS];
        int joA[NPS], joB[NPS];
        unsigned rstAm = 0, rstBm = 0;
#pragma unroll
        for (int p = 0; p < NPS; ++p) {
            float dA, dB; int jA, jB;
            {
                int idx = idxA[p], nf = (Lc - 1) - idx;
                if (k < nf) {
                    int s = idx + k;
                    dA = ts[s + 1] - ts[s]; jA = s + 1;
                    if (k + 1 == nf) rstAm |= 1u << p;
                } else {
                    int s = idx - (k - nf);
                    dA = ts[s - 1] - ts[s]; jA = s - 1;
                }
            }
            {
                int idx = idxB[p], nf = (Lc - 1) - idx;
                if (k < nf) {
                    int s = idx + k;
                    dB = ts[s + 1] - ts[s]; jB = s + 1;
                    if (k + 1 == nf) rstBm |= 1u << p;
                } else {
                    int s = idx - (k - nf);
                    dB = ts[s - 1] - ts[s]; jB = s - 1;
                }
            }
            dp[p] = pk2(dA, dB);
            joA[p] = obA[p] + jA * (Hc * Ec * 2);
            joB[p] = obB[p] + jB * (Hc * Ec * 2);
        }

        gemm1(sm, SM_Y, cg, pb);
        __syncwarp();
        gemm2_epi<0>(sm, cg, pb, dp, x0p, joA, joB, rstAm, rstBm, out);
        __syncwarp();
        gemm1(sm, SM_YIN, cg, pb);
        __syncwarp();
        gemm2_epi<1>(sm, cg, pb, dp, x0p, joA, joB, rstAm, rstBm, out);
        __syncwarp();
        gemm1(sm, SM_YIN, cg, pb);
        __syncwarp();
        gemm2_epi<2>(sm, cg, pb, dp, x0p, joA, joB, rstAm, rstBm, out);
        __syncwarp();
        gemm1(sm, SM_YIN, cg, pb);
        __syncwarp();
        gemm2_epi<3>(sm, cg, pb, dp, x0p, joA, joB, rstAm, rstBm, out);
        __syncwarp();
    }
}

extern "C" void kernel_launch(void* const* d_in, const int* in_sizes, int n_in,
                              void* d_out, int out_size) {
    const float* x   = (const float*)d_in[0];
    const float* ts  = (const float*)d_in[1];
    const float* W1  = (const float*)d_in[2];
    const float* b1  = (const float*)d_in[3];
    const float* W2  = (const float*)d_in[4];
    const float* b2  = (const float*)d_in[5];
    float* out = (float*)d_out;

    cudaFuncSetAttribute(ode_kernel, cudaFuncAttributeMaxDynamicSharedMemorySize,
                         SMEM_BYTES);
    ode_kernel<<<GRID, NT, SMEM_BYTES>>>(x, ts, W1, b1, W2, b2, out);
}

// round 13
// speedup vs baseline: 1.1614x; 1.0032x over previous
#include <cuda_runtime.h>

#define Lc   96
#define Hc   8
#define Ec   64
#define EHc  128
#define NT   256
#define NPS  3          // row-pairs per warp; 8 warps * 6 rows = 48 rows/CTA
#define GRID 128        // 128 * 48 = 6144 chains exactly
#define YP   132
#define HPP  260

constexpr int SM_W1  = 0;                     // [64][128] row-major
constexpr int SM_W2P = SM_W1 + Ec * EHc;      // [64][128] permuted
constexpr int SM_B1  = SM_W2P + Ec * EHc;
constexpr int SM_B2  = SM_B1 + EHc;
constexpr int SM_TS  = SM_B2 + Ec;
constexpr int SM_Y   = SM_TS + Lc;            // [24][132] pair-interleaved
constexpr int SM_YIN = SM_Y   + 24 * YP;
constexpr int SM_K1  = SM_YIN + 24 * YP;
constexpr int SM_K2  = SM_K1  + 24 * YP;
constexpr int SM_HP  = SM_K2  + 24 * YP;      // [24][260]
constexpr int SM_TOT = SM_HP  + 24 * HPP;
constexpr int SMEM_BYTES = SM_TOT * 4;        // ~142 KB

typedef unsigned long long ull;

__device__ __forceinline__ ull pk2(float a, float b) {
    ull r; asm("mov.b64 %0, {%1, %2};" : "=l"(r) : "f"(a), "f"(b)); return r;
}
__device__ __forceinline__ void upk2(ull v, float& a, float& b) {
    asm("mov.b64 {%0, %1}, %2;" : "=f"(a), "=f"(b) : "l"(v));
}
__device__ __forceinline__ ull f2fma(ull a, ull b, ull c) {
    ull d; asm("fma.rn.f32x2 %0, %1, %2, %3;" : "=l"(d) : "l"(a), "l"(b), "l"(c));
    return d;
}
__device__ __forceinline__ ull add2(ull a, ull b) {
    ull d; asm("add.rn.f32x2 %0, %1, %2;" : "=l"(d) : "l"(a), "l"(b)); return d;
}
__device__ __forceinline__ ull mul2(ull a, ull b) {
    ull d; asm("mul.rn.f32x2 %0, %1, %2;" : "=l"(d) : "l"(a), "l"(b)); return d;
}

// tanh(x) = (e^{2x}-1)/(e^{2x}+1), clamp |x|<=9. Abs err ~1e-7.
__device__ __forceinline__ float fast_tanh(float x) {
    float xc = fminf(fmaxf(x, -9.0f), 9.0f);
    float t;
    asm("ex2.approx.f32 %0, %1;" : "=f"(t) : "f"(xc * 2.8853900817779268f));
    float r;
    asm("rcp.approx.f32 %0, %1;" : "=f"(r) : "f"(t + 1.0f));
    return (t - 1.0f) * r;
}

// GEMM1: Hp = tanh(Yin@W1 + b1), pair-packed rows. Lane cg: cols 4cg..4cg+3.
// Hidden pair for col j stored at pair-row offset 64*(j&3) + 2*(j>>2).
__device__ __forceinline__ void gemm1(float* sm, int ybase, int cg, int pb) {
    const float* __restrict__ W1 = sm + SM_W1;
    float4 bv = *(const float4*)&sm[SM_B1 + 4 * cg];
    ull acc[NPS][4];
    {
        ull b0 = pk2(bv.x, bv.x), b1 = pk2(bv.y, bv.y);
        ull b2 = pk2(bv.z, bv.z), b3 = pk2(bv.w, bv.w);
#pragma unroll
        for (int p = 0; p < NPS; ++p) {
            acc[p][0] = b0; acc[p][1] = b1; acc[p][2] = b2; acc[p][3] = b3;
        }
    }
#pragma unroll 4
    for (int ep = 0; ep < 32; ++ep) {
        float4 wa = *(const float4*)&W1[(2 * ep) * EHc + 4 * cg];
        float4 wb = *(const float4*)&W1[(2 * ep + 1) * EHc + 4 * cg];
        ull wa0 = pk2(wa.x, wa.x), wa1 = pk2(wa.y, wa.y);
        ull wa2 = pk2(wa.z, wa.z), wa3 = pk2(wa.w, wa.w);
        ull wb0 = pk2(wb.x, wb.x), wb1 = pk2(wb.y, wb.y);
        ull wb2 = pk2(wb.z, wb.z), wb3 = pk2(wb.w, wb.w);
#pragma unroll
        for (int p = 0; p < NPS; ++p) {
            ulonglong2 yv = *(const ulonglong2*)&sm[ybase + (pb + p) * YP + 4 * ep];
            acc[p][0] = f2fma(yv.x, wa0, acc[p][0]);
            acc[p][1] = f2fma(yv.x, wa1, acc[p][1]);
            acc[p][2] = f2fma(yv.x, wa2, acc[p][2]);
            acc[p][3] = f2fma(yv.x, wa3, acc[p][3]);
            acc[p][0] = f2fma(yv.y, wb0, acc[p][0]);
            acc[p][1] = f2fma(yv.y, wb1, acc[p][1]);
            acc[p][2] = f2fma(yv.y, wb2, acc[p][2]);
            acc[p][3] = f2fma(yv.y, wb3, acc[p][3]);
        }
    }
#pragma unroll
    for (int p = 0; p < NPS; ++p) {
        float* hr = sm + SM_HP + (pb + p) * HPP;
#pragma unroll
        for (int c = 0; c < 4; ++c) {
            float a, b;
            upk2(acc[p][c], a, b);
            *(float2*)&hr[64 * c + 2 * cg] = make_float2(fast_tanh(a), fast_tanh(b));
        }
    }
}

// GEMM2 + RK4 stage. Lane cg: out cols e = 2cg, 2cg+1 (pair-packed rows).
// ST=0: K1=o;  Yin = Y + dt/3*o
// ST=1: K2=o;  Yin = Y + dt*o - dt/3*K1
// ST=2: K1 <- K1 + 3*(K2+o); Yin = Y + dt*(K1 - K2 + o)
// ST=3: yn = Y + dt/8*(K1+o); emit {x0,yn}; Y = rst ? x0 : yn
template <int ST>
__device__ __forceinline__ void gemm2_epi(float* sm, int cg, int pb,
                                          const ull dp[NPS], const float4 x0p[NPS],
                                          const int joA[NPS], const int joB[NPS],
                                          unsigned rstAm, unsigned rstBm,
                                          float* __restrict__ out) {
    const float* __restrict__ W2 = sm + SM_W2P;
    float2 b2v = *(const float2*)&sm[SM_B2 + 2 * cg];
    ull acc[NPS][2];
    {
        ull c0 = pk2(b2v.x, b2v.x), c1 = pk2(b2v.y, b2v.y);
#pragma unroll
        for (int p = 0; p < NPS; ++p) { acc[p][0] = c0; acc[p][1] = c1; }
    }
#pragma unroll 4
    for (int u = 0; u < 64; ++u) {
        float4 w = *(const float4*)&W2[u * EHc + 4 * cg];
        ull w00 = pk2(w.x, w.x), w01 = pk2(w.y, w.y);
        ull w10 = pk2(w.z, w.z), w11 = pk2(w.w, w.w);
#pragma unroll
        for (int p = 0; p < NPS; ++p) {
            ulonglong2 hv = *(const ulonglong2*)&sm[SM_HP + (pb + p) * HPP + 4 * u];
            acc[p][0] = f2fma(hv.x, w00, acc[p][0]);
            acc[p][1] = f2fma(hv.x, w01, acc[p][1]);
            acc[p][0] = f2fma(hv.y, w10, acc[p][0]);
            acc[p][1] = f2fma(hv.y, w11, acc[p][1]);
        }
    }

    const ull THIRDC  = pk2(1.0f / 3.0f, 1.0f / 3.0f);
    const ull NTHIRDC = pk2(-1.0f / 3.0f, -1.0f / 3.0f);
    const ull EIGHTHC = pk2(0.125f, 0.125f);
    const ull THREEC  = pk2(3.0f, 3.0f);
    const ull NEGONEC = pk2(-1.0f, -1.0f);

#pragma unroll
    for (int p = 0; p < NPS; ++p) {
        float* yr  = sm + SM_Y   + (pb + p) * YP + 4 * cg;
        float* yi  = sm + SM_YIN + (pb + p) * YP + 4 * cg;
        float* k1r = sm + SM_K1  + (pb + p) * YP + 4 * cg;
        float* k2r = sm + SM_K2  + (pb + p) * YP + 4 * cg;
        ulonglong2 yv = *(const ulonglong2*)yr;
        ull o0 = acc[p][0], o1 = acc[p][1];
        ull d = dp[p];
        if (ST == 0) {
            *(ulonglong2*)k1r = make_ulonglong2(o0, o1);
            ull d3 = mul2(d, THIRDC);
            *(ulonglong2*)yi = make_ulonglong2(f2fma(o0, d3, yv.x),
                                               f2fma(o1, d3, yv.y));
        } else if (ST == 1) {
            ulonglong2 k1 = *(const ulonglong2*)k1r;
            *(ulonglong2*)k2r = make_ulonglong2(o0, o1);
            ull nd3 = mul2(d, NTHIRDC);
            ull t0 = f2fma(k1.x, nd3, yv.x);
            ull t1 = f2fma(k1.y, nd3, yv.y);
            *(ulonglong2*)yi = make_ulonglong2(f2fma(o0, d, t0), f2fma(o1, d, t1));
        } else if (ST == 2) {
            ulonglong2 k1 = *(const ulonglong2*)k1r;
            ulonglong2 k2 = *(const ulonglong2*)k2r;
            ull s0 = add2(k2.x, o0), s1 = add2(k2.y, o1);
            *(ulonglong2*)k1r = make_ulonglong2(f2fma(s0, THREEC, k1.x),
                                                f2fma(s1, THREEC, k1.y));
            ull a0 = add2(k1.x, o0), a1 = add2(k1.y, o1);
            ull u0 = f2fma(k2.x, NEGONEC, a0);
            ull u1 = f2fma(k2.y, NEGONEC, a1);
            *(ulonglong2*)yi = make_ulonglong2(f2fma(u0, d, yv.x),
                                               f2fma(u1, d, yv.y));
        } else {
            ulonglong2 k1 = *(const ulonglong2*)k1r;
            ull d8 = mul2(d, EIGHTHC);
            ull yn0 = f2fma(add2(k1.x, o0), d8, yv.x);
            ull yn1 = f2fma(add2(k1.y, o1), d8, yv.y);
            float yA0, yB0, yA1, yB1;
            upk2(yn0, yA0, yB0);
            upk2(yn1, yA1, yB1);
            *(float4*)&out[joA[p]] = make_float4(x0p[p].x, yA0, x0p[p].y, yA1);
            *(float4*)&out[joB[p]] = make_float4(x0p[p].z, yB0, x0p[p].w, yB1);
            bool rA = (rstAm >> p) & 1, rB = (rstBm >> p) & 1;
            *(float4*)yr = make_float4(rA ? x0p[p].x : yA0, rB ? x0p[p].z : yB0,
                                       rA ? x0p[p].y : yA1, rB ? x0p[p].w : yB1);
        }
    }
}

__global__ void __launch_bounds__(NT, 1)
ode_kernel(const float* __restrict__ x, const float* __restrict__ tsg,
           const float* __restrict__ W1g, const float* __restrict__ b1g,
           const float* __restrict__ W2g, const float* __restrict__ b2g,
           float* __restrict__ out) {
    extern __shared__ float sm[];
    const int tid = threadIdx.x;
    const int cg  = tid & 31;
    const int wid = tid >> 5;
    const int pb  = wid * NPS;

    // W1 row-major copy
    for (int t = tid; t < Ec * EHc; t += NT) sm[SM_W1 + t] = W1g[t];
    // W2 permuted for the HP layout: W2P[u][4c+k] = W2[j0(u)+4*(k>>1)][2c+(k&1)],
    // j0(u) = 4*(((4u)&63)>>1) + ((4u)>>6)
    for (int t = tid; t < 64 * 128; t += NT) {
        int u = t >> 7, p = t & 127, c = p >> 2, k = p & 3;
        int j0 = 4 * (((4 * u) & 63) >> 1) + ((4 * u) >> 6);
        int j = j0 + 4 * (k >> 1);
        sm[SM_W2P + t] = W2g[j * Ec + 2 * c + (k & 1)];
    }
    if (tid < EHc) sm[SM_B1 + tid] = b1g[tid];
    if (tid < Ec)  sm[SM_B2 + tid] = b2g[tid];
    if (tid < Lc)  sm[SM_TS + tid] = tsg[tid];

    // chain metadata: 48 rows/CTA, exact fit (no inactive slots).
    // q = idx*64 + b*8 + h; lane cg owns cols 2cg, 2cg+1.
    const int qbase = blockIdx.x * 48 + wid * (2 * NPS);
    float4 x0p[NPS];
    int obA[NPS], obB[NPS], idxA[NPS], idxB[NPS];
#pragma unroll
    for (int p = 0; p < NPS; ++p) {
        int qA = qbase + 2 * p, qB = qbase + 2 * p + 1;
        idxA[p] = qA >> 6; idxB[p] = qB >> 6;
        int bA = (qA >> 3) & 7, hA = qA & 7;
        int bB = (qB >> 3) & 7, hB = qB & 7;
        float2 xA = *(const float2*)&x[((bA * Lc + idxA[p]) * Hc + hA) * Ec + 2 * cg];
        float2 xB = *(const float2*)&x[((bB * Lc + idxB[p]) * Hc + hB) * Ec + 2 * cg];
        x0p[p] = make_float4(xA.x, xA.y, xB.x, xB.y);
        obA[p] = bA * (Lc * Lc * Hc * Ec * 2) + idxA[p] * (Lc * Hc * Ec * 2) +
                 hA * (Ec * 2) + 4 * cg;
        obB[p] = bB * (Lc * Lc * Hc * Ec * 2) + idxB[p] * (Lc * Hc * Ec * 2) +
                 hB * (Ec * 2) + 4 * cg;
        *(float4*)&sm[SM_Y + (pb + p) * YP + 4 * cg] =
            make_float4(xA.x, xB.x, xA.y, xB.y);
        *(float4*)&out[obA[p] + idxA[p] * (Hc * Ec * 2)] =
            make_float4(xA.x, xA.x, xA.y, xA.y);
        *(float4*)&out[obB[p] + idxB[p] * (Hc * Ec * 2)] =
            make_float4(xB.x, xB.x, xB.y, xB.y);
    }
    __syncthreads();   // weights + ts visible; warps free-run

    const float* ts = sm + SM_TS;

    // 95 lockstep RK4 steps: fwd k < nf = 95-idx (emit j=s+1), reset to x0,
    // then bwd (dt<0, emit j=s-1). Rows warp-private -> __syncwarp only.
    for (int k = 0; k < Lc - 1; ++k) {
        ull dp[NPS];
        int joA[NPS], joB[NPS];
        unsigned rstAm = 0, rstBm = 0;
#pragma unroll
        for (int p = 0; p < NPS; ++p) {
            float dA, dB; int jA, jB;
            {
                int idx = idxA[p], nf = (Lc - 1) - idx;
                if (k < nf) {
                    int s = idx + k;
                    dA = ts[s + 1] - ts[s]; jA = s + 1;
                    if (k + 1 == nf) rstAm |= 1u << p;
                } else {
                    int s = idx - (k - nf);
                    dA = ts[s - 1] - ts[s]; jA = s - 1;
                }
            }
            {
                int idx = idxB[p], nf = (Lc - 1) - idx;
                if (k < nf) {
                    int s = idx + k;
                    dB = ts[s + 1] - ts[s]; jB = s + 1;
                    if (k + 1 == nf) rstBm |= 1u << p;
                } else {
                    int s = idx - (k - nf);
                    dB = ts[s - 1] - ts[s]; jB = s - 1;
                }
            }
            dp[p] = pk2(dA, dB);
            joA[p] = obA[p] + jA * (Hc * Ec * 2);
            joB[p] = obB[p] + jB * (Hc * Ec * 2);
        }

        gemm1(sm, SM_Y, cg, pb);
        __syncwarp();
        gemm2_epi<0>(sm, cg, pb, dp, x0p, joA, joB, rstAm, rstBm, out);
        __syncwarp();
        gemm1(sm, SM_YIN, cg, pb);
        __syncwarp();
        gemm2_epi<1>(sm, cg, pb, dp, x0p, joA, joB, rstAm, rstBm, out);
        __syncwarp();
        gemm1(sm, SM_YIN, cg, pb);
        __syncwarp();
        gemm2_epi<2>(sm, cg, pb, dp, x0p, joA, joB, rstAm, rstBm, out);
        __syncwarp();
        gemm1(sm, SM_YIN, cg, pb);
        __syncwarp();
        gemm2_epi<3>(sm, cg, pb, dp, x0p, joA, joB, rstAm, rstBm, out);
        __syncwarp();
    }
}

extern "C" void kernel_launch(void* const* d_in, const int* in_sizes, int n_in,
                              void* d_out, int out_size) {
    const float* x   = (const float*)d_in[0];
    const float* ts  = (const float*)d_in[1];
    const float* W1  = (const float*)d_in[2];
    const float* b1  = (const float*)d_in[3];
    const float* W2  = (const float*)d_in[4];
    const float* b2  = (const float*)d_in[5];
    float* out = (float*)d_out;

    cudaFuncSetAttribute(ode_kernel, cudaFuncAttributeMaxDynamicSharedMemorySize,
                         SMEM_BYTES);
    ode_kernel<<<GRID, NT, SMEM_BYTES>>>(x, ts, W1, b1, W2, b2, out);
}